// round 2
// baseline (speedup 1.0000x reference)
#include <cuda_runtime.h>

// fusedmax(x) = sparsemax(prox_TV1D(x, alpha=1)), row-wise. B=4096, N=512, fp32.
// 128 blocks x 32 threads; each lane owns one row, transposed in shared
// (pad-33: coalesced load/store conflict-free; hot loop bank = (c+lane)%32,
// near-conflict-free since lanes' positions stay correlated).

#define NROWS 4096
#define NCOLS 512
#define ROWS_PER_BLK 32
#define PAD 33
#define SMEM_BYTES (NCOLS * PAD * 4)

__global__ __launch_bounds__(32, 1)
void fusedmax_kernel(const float* __restrict__ x, float* __restrict__ out) {
    extern __shared__ float ys[];            // [NCOLS][PAD]
    __shared__ float taus[ROWS_PER_BLK];

    const int lane    = threadIdx.x;
    const int rowBase = blockIdx.x * ROWS_PER_BLK;
    const float lam   = 1.0f;
    const int n       = NCOLS;

    // ---- coalesced load, transposed into shared ----
    const float* src = x + (size_t)rowBase * NCOLS;
    #pragma unroll 4
    for (int j = 0; j < ROWS_PER_BLK * NCOLS; j += 32) {
        int idx = j + lane;
        int r = idx >> 9;
        int c = idx & (NCOLS - 1);
        ys[c * PAD + r] = src[idx];
    }
    __syncwarp();

    // ---- Condat TV1D, branch-structured, in-place ----
    // In-place safety: flushes write [k0..hi] with hi < all future read
    // indices, except reads of position n-1 which use the cached register.
    const float ylast = ys[(n - 1) * PAD + lane];

    {
        int   k = 0, k0 = 0, km = 0, kp = 0;
        float vmin = ys[0 * PAD + lane] - lam;
        float vmax = vmin + 2.0f * lam;
        float umin = lam, umax = -lam;
        float yn = ys[1 * PAD + lane];          // prefetched y[k+1]

        while (true) {
            if (k == n - 1) {
                // ---------- end phase ----------
                if (umin < 0.0f) {
                    int nk = km + 1; if (nk > n - 1) nk = n - 1;
                    const float ynk = (nk >= n - 1) ? ylast : ys[nk * PAD + lane];
                    yn = (nk + 1 >= n - 1) ? ylast : ys[(nk + 1) * PAD + lane];
                    for (int i = k0; i <= km; i++) ys[i * PAD + lane] = vmin;
                    k = k0 = km = nk;            // kp, vmax untouched
                    vmin = ynk;
                    umin = lam;
                    umax = ynk + lam - vmax;
                } else if (umax > 0.0f) {
                    int nk = kp + 1; if (nk > n - 1) nk = n - 1;
                    const float ynk = (nk >= n - 1) ? ylast : ys[nk * PAD + lane];
                    yn = (nk + 1 >= n - 1) ? ylast : ys[(nk + 1) * PAD + lane];
                    for (int i = k0; i <= kp; i++) ys[i * PAD + lane] = vmax;
                    k = k0 = kp = nk;            // km, vmin untouched
                    vmax = ynk;
                    umax = -lam;
                    umin = ynk - lam - vmin;
                } else {
                    const float val = vmin + umin / (float)(k - k0 + 1);
                    for (int i = k0; i <= n - 1; i++) ys[i * PAD + lane] = val;
                    break;
                }
            } else {
                const float ynext = yn;
                if (ynext + umin < vmin - lam) {
                    // ---------- negative jump ----------
                    int nk = km + 1; if (nk > n - 1) nk = n - 1;
                    const float ynk = (nk >= n - 1) ? ylast : ys[nk * PAD + lane];
                    yn = (nk + 1 >= n - 1) ? ylast : ys[(nk + 1) * PAD + lane];
                    for (int i = k0; i <= km; i++) ys[i * PAD + lane] = vmin;
                    k = k0 = km = kp = nk;
                    vmin = ynk;
                    vmax = ynk + 2.0f * lam;
                    umin = lam;
                    umax = -lam;
                } else if (ynext + umax > vmax + lam) {
                    // ---------- positive jump ----------
                    int nk = kp + 1; if (nk > n - 1) nk = n - 1;
                    const float ynk = (nk >= n - 1) ? ylast : ys[nk * PAD + lane];
                    yn = (nk + 1 >= n - 1) ? ylast : ys[(nk + 1) * PAD + lane];
                    for (int i = k0; i <= kp; i++) ys[i * PAD + lane] = vmax;
                    k = k0 = km = kp = nk;
                    vmax = ynk;
                    vmin = ynk - 2.0f * lam;
                    umin = lam;
                    umax = -lam;
                } else {
                    // ---------- plain accumulation (hot path) ----------
                    k = k + 1;
                    // prefetch next element ASAP to hide LDS latency
                    yn = (k + 1 >= n - 1) ? ylast : ys[(k + 1) * PAD + lane];
                    const float umin_t = umin + ynext - vmin;
                    const float umax_t = umax + ynext - vmax;
                    if (umin_t >= lam) {
                        vmin += (umin_t - lam) / (float)(k - k0 + 1);
                        umin = lam;
                        km = k;
                    } else {
                        umin = umin_t;
                    }
                    if (umax_t <= -lam) {
                        vmax += (umax_t + lam) / (float)(k - k0 + 1);
                        umax = -lam;
                        kp = k;
                    } else {
                        umax = umax_t;
                    }
                }
            }
        }
    }
    __syncwarp();

    // ---- sparsemax threshold via Michelot (exact fixed point) ----
    {
        float sum = 0.0f;
        #pragma unroll 8
        for (int i = 0; i < n; i++) sum += ys[i * PAD + lane];
        float tau = (sum - 1.0f) / (float)n;
        int c_prev = n;
        for (int it = 0; it < n; it++) {
            float s = 0.0f;
            int   c = 0;
            #pragma unroll 8
            for (int i = 0; i < n; i++) {
                float v = ys[i * PAD + lane];
                if (v > tau) { s += v; c++; }
            }
            if (c == c_prev) break;
            tau = (s - 1.0f) / (float)c;
            c_prev = c;
        }
        taus[lane] = tau;
    }
    __syncwarp();

    // ---- coalesced store of max(z - tau, 0) ----
    float* dst = out + (size_t)rowBase * NCOLS;
    #pragma unroll 4
    for (int j = 0; j < ROWS_PER_BLK * NCOLS; j += 32) {
        int idx = j + lane;
        int r = idx >> 9;
        int c = idx & (NCOLS - 1);
        float v = ys[c * PAD + r] - taus[r];
        dst[idx] = (v > 0.0f) ? v : 0.0f;
    }
}

extern "C" void kernel_launch(void* const* d_in, const int* in_sizes, int n_in,
                              void* d_out, int out_size) {
    (void)in_sizes; (void)n_in; (void)out_size;
    const float* x   = (const float*)d_in[0];
    float*       out = (float*)d_out;

    cudaFuncSetAttribute(fusedmax_kernel,
                         cudaFuncAttributeMaxDynamicSharedMemorySize,
                         SMEM_BYTES);
    fusedmax_kernel<<<NROWS / ROWS_PER_BLK, ROWS_PER_BLK, SMEM_BYTES>>>(x, out);
}

// round 3
// speedup vs baseline: 1.3640x; 1.3640x over previous
#include <cuda_runtime.h>

// fusedmax(x) = sparsemax(prox_TV1D(x, alpha=1)), row-wise. B=4096, N=512, fp32.
// 128 blocks x 32 threads; each lane owns one row, transposed in shared.
// Main loop (Condat) only READS y; segment results are logged run-length
// encoded; sparsemax runs on the RLE; final reconstruction + coalesced store.

#define NROWS 4096
#define NCOLS 512
#define ROWS_PER_BLK 32
#define PAD 33
#define YS_FLOATS (NCOLS * PAD)
#define SEG_WORDS (NCOLS * 32)
#define SMEM_BYTES ((YS_FLOATS + 2 * SEG_WORDS) * 4)

__global__ __launch_bounds__(32, 1)
void fusedmax_kernel(const float* __restrict__ x, float* __restrict__ out) {
    extern __shared__ float smem[];
    float* ys      = smem;                         // [NCOLS][PAD]
    float* seg_val = smem + YS_FLOATS;             // [entry][lane]
    int*   seg_end = (int*)(smem + YS_FLOATS + SEG_WORDS);

    const int lane    = threadIdx.x;
    const int rowBase = blockIdx.x * ROWS_PER_BLK;
    const float lam   = 1.0f;
    const int n       = NCOLS;

    // ---- coalesced load, transposed into shared ----
    const float* src = x + (size_t)rowBase * NCOLS;
    #pragma unroll 4
    for (int j = 0; j < ROWS_PER_BLK * NCOLS; j += 32) {
        int idx = j + lane;
        int r = idx >> 9;
        int c = idx & (NCOLS - 1);
        ys[c * PAD + r] = src[idx];
    }
    __syncwarp();

    float* yl = ys + lane;                         // yl[c*PAD] == y[c]

    // ---- Condat TV1D: read-only scan, RLE segment log ----
    int   k = 0, k0 = 0, km = 0, kp = 0;
    float vmin = yl[0] - lam;
    float vmax = vmin + 2.0f * lam;
    float umin = lam, umax = -lam;
    float cnt_f = 1.0f;                            // == k - k0 + 1
    float yn = yl[1 * PAD];                        // prefetched y[k+1]
    int   nseg = 0;
    bool  done = false;

    while (__ballot_sync(0xFFFFFFFFu, !done)) {
        if (!done) {
            const bool  at_end = (k == n - 1);
            const float ynext  = yn;
            const bool neg = at_end ? (umin < 0.0f)
                                    : (ynext + umin < vmin - lam);
            const bool pos = !neg && (at_end ? (umax > 0.0f)
                                             : (ynext + umax > vmax + lam));
            const bool fin  = !neg && !pos && at_end;
            const bool jump = neg || pos;

            int nk = neg ? (km + 1) : (pos ? (kp + 1) : (k + 1));
            nk = min(nk, n - 1);
            const float ynk = jump ? yl[nk * PAD] : ynext;
            yn = yl[min(nk + 1, n - 1) * PAD];     // prefetch next

            if (jump | fin) {                      // O(1) log append
                seg_end[nseg * 32 + lane] = neg ? km : (pos ? kp : (n - 1));
                seg_val[nseg * 32 + lane] =
                    pos ? vmax
                        : (fin ? vmin + __fdividef(umin, cnt_f) : vmin);
                nseg++;
            }

            if (fin) {
                done = true;
            } else if (jump) {
                k = nk; k0 = nk; cnt_f = 1.0f;
                if (neg) {
                    km = nk; vmin = ynk; umin = lam;
                    if (at_end) { umax = ynk + lam - vmax; }   // vmax,kp keep
                    else        { kp = nk; vmax = ynk + 2.0f * lam; umax = -lam; }
                } else {
                    kp = nk; vmax = ynk; umax = -lam;
                    if (at_end) { umin = ynk - lam - vmin; }   // vmin,km keep
                    else        { km = nk; vmin = ynk - 2.0f * lam; umin = lam; }
                }
            } else {                               // mid (hot path)
                k = nk; cnt_f += 1.0f;
                const float umin_t = umin + ynext - vmin;
                const float umax_t = umax + ynext - vmax;
                if (umin_t >= lam) {
                    vmin += __fdividef(umin_t - lam, cnt_f);
                    umin = lam; km = nk;
                } else {
                    umin = umin_t;
                }
                if (umax_t <= -lam) {
                    vmax += __fdividef(umax_t + lam, cnt_f);
                    umax = -lam; kp = nk;
                } else {
                    umax = umax_t;
                }
            }
        }
    }
    __syncwarp();

    // ---- sparsemax tau via Michelot on the RLE segments ----
    float tau;
    {
        float sum = 0.0f;
        int prev = -1;
        for (int j = 0; j < nseg; j++) {
            int e = seg_end[j * 32 + lane];
            sum += (float)(e - prev) * seg_val[j * 32 + lane];
            prev = e;
        }
        tau = (sum - 1.0f) * (1.0f / (float)NCOLS);
        int c_prev = n;
        for (int it = 0; it < n; it++) {
            float s = 0.0f;
            int   c = 0;
            int   pr = -1;
            for (int j = 0; j < nseg; j++) {
                int   e = seg_end[j * 32 + lane];
                float v = seg_val[j * 32 + lane];
                int len = e - pr; pr = e;
                if (v > tau) { s += (float)len * v; c += len; }
            }
            if (c == c_prev) break;
            tau = (s - 1.0f) / (float)c;
            c_prev = c;
        }
    }
    __syncwarp();

    // ---- reconstruct max(val - tau, 0) into ys ----
    {
        int   j = 0;
        int   e = seg_end[lane];
        float v = seg_val[lane] - tau;
        for (int c = 0; c < n; c++) {
            if (c > e) {
                j++;
                e = seg_end[j * 32 + lane];
                v = seg_val[j * 32 + lane] - tau;
            }
            yl[c * PAD] = fmaxf(v, 0.0f);
        }
    }
    __syncwarp();

    // ---- coalesced store ----
    float* dst = out + (size_t)rowBase * NCOLS;
    #pragma unroll 4
    for (int j = 0; j < ROWS_PER_BLK * NCOLS; j += 32) {
        int idx = j + lane;
        int r = idx >> 9;
        int c = idx & (NCOLS - 1);
        dst[idx] = ys[c * PAD + r];
    }
}

extern "C" void kernel_launch(void* const* d_in, const int* in_sizes, int n_in,
                              void* d_out, int out_size) {
    (void)in_sizes; (void)n_in; (void)out_size;
    const float* x   = (const float*)d_in[0];
    float*       out = (float*)d_out;

    cudaFuncSetAttribute(fusedmax_kernel,
                         cudaFuncAttributeMaxDynamicSharedMemorySize,
                         SMEM_BYTES);
    fusedmax_kernel<<<NROWS / ROWS_PER_BLK, ROWS_PER_BLK, SMEM_BYTES>>>(x, out);
}

// round 4
// speedup vs baseline: 2.3734x; 1.7400x over previous
#include <cuda_runtime.h>

// fusedmax(x) = sparsemax(prox_TV1D(x, alpha=1)), row-wise. B=4096, N=512, fp32.
// 128 blocks x 32 threads; each lane owns one row, transposed in shared.
// Condat scan is a single straight-line (branch-free) body with a
// warp-uniform loop; segments are RLE-logged; sparsemax runs on the RLE.

#define NROWS 4096
#define NCOLS 512
#define ROWS_PER_BLK 32
#define PAD 33
#define YS_FLOATS (NCOLS * PAD)
#define SEG_ENTRIES 516                 // 512 max live + slack for done-lane stores
#define SEG_WORDS (SEG_ENTRIES * 32)
#define SMEM_BYTES ((YS_FLOATS + 2 * SEG_WORDS) * 4)

__global__ __launch_bounds__(32, 1)
void fusedmax_kernel(const float* __restrict__ x, float* __restrict__ out) {
    extern __shared__ float smem[];
    float* ys      = smem;                          // [NCOLS][PAD]
    float* seg_val = smem + YS_FLOATS;              // [entry][lane]
    int*   seg_end = (int*)(smem + YS_FLOATS + SEG_WORDS);

    const int lane    = threadIdx.x;
    const int rowBase = blockIdx.x * ROWS_PER_BLK;
    const float lam   = 1.0f;
    const int n       = NCOLS;

    // ---- coalesced load, transposed into shared ----
    const float* src = x + (size_t)rowBase * NCOLS;
    #pragma unroll 4
    for (int j = 0; j < ROWS_PER_BLK * NCOLS; j += 32) {
        int idx = j + lane;
        int r = idx >> 9;
        int c = idx & (NCOLS - 1);
        ys[c * PAD + r] = src[idx];
    }
    __syncwarp();

    float* yl = ys + lane;                          // yl[c*PAD] == y[c]

    // ---- Condat TV1D: branch-free body, warp-uniform loop ----
    int   k = 0, k0 = 0, km = 0, kp = 0;
    float vmin = yl[0] - lam;
    float vmax = vmin + 2.0f * lam;
    float umin = lam, umax = -lam;
    float cnt_f = 1.0f;                             // k - k0 + 1
    float yn = yl[1 * PAD];                         // prefetched y[k+1]
    int   nseg = 0;
    bool  done = false;

    while (__any_sync(0xFFFFFFFFu, !done)) {
        const bool at_end = (k == n - 1);

        const bool neg = at_end ? (umin < 0.0f) : (yn + umin < vmin - lam);
        const bool pos = (!neg) & (at_end ? (umax > 0.0f)
                                          : (yn + umax > vmax + lam));
        const bool jump = neg | pos;
        const bool fin  = (!jump) & at_end;
        const bool eneg = neg & at_end;
        const bool epos = pos & at_end;

        int nk = neg ? (km + 1) : (pos ? (kp + 1) : (k + 1));
        nk = min(nk, n - 1);

        const float ynk = yl[nk * PAD];                   // == yn for mid lanes
        yn = yl[min(nk + 1, n - 1) * PAD];                // prefetch next

        // --- RLE log: unconditional stores, conditional bump ---
        const int   e_out = neg ? km : (pos ? kp : (n - 1));
        const float v_out = pos ? vmax
                                : (fin ? vmin + umin * __frcp_rn(cnt_f) : vmin);
        seg_end[nseg * 32 + lane] = e_out;
        seg_val[nseg * 32 + lane] = v_out;
        nseg += (int)((jump | fin) & !done);
        done |= fin;

        // --- mid candidates (valid when !jump) ---
        const float cnt_new = jump ? 1.0f : (cnt_f + 1.0f);
        const float inv_cnt = __frcp_rn(cnt_new);
        const float umin_t  = umin + ynk - vmin;
        const float umax_t  = umax + ynk - vmax;
        const bool  c1 = (umin_t >= lam);
        const bool  c2 = (umax_t <= -lam);
        const float vmin_mid = c1 ? vmin + (umin_t - lam) * inv_cnt : vmin;
        const float umin_mid = c1 ? lam : umin_t;
        const int   km_mid   = c1 ? nk : km;
        const float vmax_mid = c2 ? vmax + (umax_t + lam) * inv_cnt : vmax;
        const float umax_mid = c2 ? -lam : umax_t;
        const int   kp_mid   = c2 ? nk : kp;

        // --- jump candidates (valid when jump) ---
        const float vmin_j = neg ? ynk : (epos ? vmin : ynk - 2.0f * lam);
        const float vmax_j = pos ? ynk : (eneg ? vmax : ynk + 2.0f * lam);
        const float umin_j = epos ? (ynk - lam - vmin) : lam;
        const float umax_j = eneg ? (ynk + lam - vmax) : -lam;
        const int   km_j   = epos ? km : nk;
        const int   kp_j   = eneg ? kp : nk;

        // --- merge ---
        vmin = jump ? vmin_j : vmin_mid;
        vmax = jump ? vmax_j : vmax_mid;
        umin = jump ? umin_j : umin_mid;
        umax = jump ? umax_j : umax_mid;
        km   = jump ? km_j   : km_mid;
        kp   = jump ? kp_j   : kp_mid;
        k0   = jump ? nk : k0;
        k    = nk;
        cnt_f = cnt_new;
    }
    __syncwarp();

    // ---- sparsemax tau via Michelot on the RLE segments ----
    float tau;
    {
        float sum = 0.0f;
        int prev = -1;
        for (int j = 0; j < nseg; j++) {
            int e = seg_end[j * 32 + lane];
            sum += (float)(e - prev) * seg_val[j * 32 + lane];
            prev = e;
        }
        tau = (sum - 1.0f) * (1.0f / (float)NCOLS);
        int c_prev = n;
        for (int it = 0; it < n; it++) {
            float s = 0.0f;
            int   c = 0;
            int   pr = -1;
            for (int j = 0; j < nseg; j++) {
                int   e = seg_end[j * 32 + lane];
                float v = seg_val[j * 32 + lane];
                int len = e - pr; pr = e;
                bool sup = (v > tau);
                s += sup ? (float)len * v : 0.0f;
                c += sup ? len : 0;
            }
            if (c == c_prev) break;
            tau = (s - 1.0f) / (float)c;
            c_prev = c;
        }
    }
    __syncwarp();

    // ---- reconstruct max(val - tau, 0) into ys (branch-free walk) ----
    {
        int j = 0;
        int e = seg_end[lane];
        float v = seg_val[lane];
        yl[0] = fmaxf(v - tau, 0.0f);
        for (int c = 1; c < n; c++) {
            j += (int)(c > e);                      // segments have len >= 1
            e = seg_end[j * 32 + lane];
            v = seg_val[j * 32 + lane];
            yl[c * PAD] = fmaxf(v - tau, 0.0f);
        }
    }
    __syncwarp();

    // ---- coalesced store ----
    float* dst = out + (size_t)rowBase * NCOLS;
    #pragma unroll 4
    for (int j = 0; j < ROWS_PER_BLK * NCOLS; j += 32) {
        int idx = j + lane;
        int r = idx >> 9;
        int c = idx & (NCOLS - 1);
        dst[idx] = ys[c * PAD + r];
    }
}

extern "C" void kernel_launch(void* const* d_in, const int* in_sizes, int n_in,
                              void* d_out, int out_size) {
    (void)in_sizes; (void)n_in; (void)out_size;
    const float* x   = (const float*)d_in[0];
    float*       out = (float*)d_out;

    cudaFuncSetAttribute(fusedmax_kernel,
                         cudaFuncAttributeMaxDynamicSharedMemorySize,
                         SMEM_BYTES);
    fusedmax_kernel<<<NROWS / ROWS_PER_BLK, ROWS_PER_BLK, SMEM_BYTES>>>(x, out);
}

// round 7
// speedup vs baseline: 2.4915x; 1.0497x over previous
#include <cuda_runtime.h>

// fusedmax(x) = sparsemax(prox_TV1D(x, alpha=1)), row-wise. B=4096, N=512, fp32.
// 128 blocks x 32 threads; each lane owns one row, transposed in shared.
// Branch-free Condat body with per-lane divergent exit; RLE segment log
// packed 64-bit; sparsemax (Michelot) on the RLE; prefetched reconstruction.

#define NROWS 4096
#define NCOLS 512
#define ROWS_PER_BLK 32
#define PAD 33
#define YS_FLOATS (NCOLS * PAD)
#define SEG_ENTRIES 517
#define SMEM_BYTES (YS_FLOATS * 4 + SEG_ENTRIES * 32 * 8)

typedef unsigned long long ull;

__global__ __launch_bounds__(32, 1)
void fusedmax_kernel(const float* __restrict__ x, float* __restrict__ out) {
    extern __shared__ float smem[];
    float* ys   = smem;                                   // [NCOLS][PAD]
    ull*   segb = (ull*)(smem + YS_FLOATS);               // [entry][lane]

    const int lane    = threadIdx.x;
    const int rowBase = blockIdx.x * ROWS_PER_BLK;
    const float lam   = 1.0f;
    const int n       = NCOLS;

    // ---- coalesced load, transposed into shared ----
    const float* src = x + (size_t)rowBase * NCOLS;
    #pragma unroll 4
    for (int j = 0; j < ROWS_PER_BLK * NCOLS; j += 32) {
        int idx = j + lane;
        int r = idx >> 9;
        int c = idx & (NCOLS - 1);
        ys[c * PAD + r] = src[idx];
    }
    __syncwarp();

    float* yl   = ys + lane;                              // yl[c*PAD] == y[c]
    ull*   segl = segb + lane;                            // segl[e*32]

    // ---- Condat TV1D: branch-free body, per-lane exit ----
    int   k = 0, km = 0, kp = 0;
    float vmin = yl[0] - lam;
    float vmax = vmin + 2.0f * lam;
    float umin = lam, umax = -lam;
    float cnt_f = 1.0f;                                   // k - k0 + 1
    float yn = yl[1 * PAD];                               // prefetched y[k+1]
    int   nseg = 0;

    while (true) {
        // early, off-critical-path speculative work
        const float inv_spec = __frcp_rn(cnt_f + 1.0f);   // rcp(cnt+1) for mid
        const float inv_cur  = __frcp_rn(cnt_f);          // for fin value

        const float ycur = yn;                            // y[k+1] snapshot
        const bool at_end = (k == n - 1);
        const bool neg = at_end ? (umin < 0.0f) : (ycur + umin < vmin - lam);
        const bool pos = (!neg) & (at_end ? (umax > 0.0f)
                                          : (ycur + umax > vmax + lam));
        const bool jump = neg | pos;
        const bool fin  = (!jump) & at_end;
        const bool eneg = neg & at_end;
        const bool epos = pos & at_end;

        int nk = neg ? (km + 1) : (pos ? (kp + 1) : (k + 1));
        nk = min(nk, n - 1);

        const float ynk = yl[nk * PAD];                   // needed by jump path
        yn = yl[min(nk + 1, n - 1) * PAD];                // prefetch next

        // --- RLE log: unconditional 64-bit store (clamped), conditional bump ---
        const int   e_out = neg ? km : (pos ? kp : (n - 1));
        const float v_out = pos ? vmax
                                : (fin ? fmaf(umin, inv_cur, vmin) : vmin);
        segl[min(nseg, SEG_ENTRIES - 1) * 32] =
            ((ull)(unsigned)e_out << 32) | (ull)__float_as_uint(v_out);
        nseg += (int)(jump | fin);

        if (fin) break;

        // --- mid candidates: use ycur (register) — equals ynk when !jump ---
        const float inv_cnt = jump ? 1.0f : inv_spec;
        const float umin_t  = umin + ycur - vmin;
        const float umax_t  = umax + ycur - vmax;
        const bool  c1 = (umin_t >= lam);
        const bool  c2 = (umax_t <= -lam);
        const float vmin_mid = c1 ? fmaf(umin_t - lam, inv_cnt, vmin) : vmin;
        const float umin_mid = c1 ? lam : umin_t;
        const int   km_mid   = c1 ? nk : km;
        const float vmax_mid = c2 ? fmaf(umax_t + lam, inv_cnt, vmax) : vmax;
        const float umax_mid = c2 ? -lam : umax_t;
        const int   kp_mid   = c2 ? nk : kp;

        // --- jump candidates (need ynk from LDS) ---
        const float vmin_j = neg ? ynk : (epos ? vmin : ynk - 2.0f * lam);
        const float vmax_j = pos ? ynk : (eneg ? vmax : ynk + 2.0f * lam);
        const float umin_j = epos ? (ynk - lam - vmin) : lam;
        const float umax_j = eneg ? (ynk + lam - vmax) : -lam;
        const int   km_j   = epos ? km : nk;
        const int   kp_j   = eneg ? kp : nk;

        // --- merge ---
        vmin = jump ? vmin_j : vmin_mid;
        vmax = jump ? vmax_j : vmax_mid;
        umin = jump ? umin_j : umin_mid;
        umax = jump ? umax_j : umax_mid;
        km   = jump ? km_j   : km_mid;
        kp   = jump ? kp_j   : kp_mid;
        cnt_f = jump ? 1.0f : (cnt_f + 1.0f);
        k    = nk;
    }

    // ---- sparsemax tau via Michelot on the RLE segments (lane-local) ----
    float tau;
    {
        float sum = 0.0f;
        int prev = -1;
        for (int j = 0; j < nseg; j++) {
            ull w = segl[j * 32];
            int e = (int)(w >> 32);
            sum += (float)(e - prev) * __uint_as_float((unsigned)w);
            prev = e;
        }
        tau = (sum - 1.0f) * (1.0f / (float)NCOLS);
        int c_prev = n;
        for (int it = 0; it < n; it++) {
            float s = 0.0f;
            int   c = 0;
            int   pr = -1;
            for (int j = 0; j < nseg; j++) {
                ull   w = segl[j * 32];
                int   e = (int)(w >> 32);
                float v = __uint_as_float((unsigned)w);
                int len = e - pr; pr = e;
                bool sup = (v > tau);
                s += sup ? (float)len * v : 0.0f;
                c += sup ? len : 0;
            }
            if (c == c_prev) break;
            tau = (s - 1.0f) / (float)c;
            c_prev = c;
        }
    }

    // ---- reconstruct max(val - tau, 0) into ys (prefetched walk) ----
    {
        int j = 0;
        ull w  = segl[0];
        ull wn = segl[32];                         // prefetch next entry
        int   e = (int)(w >> 32);
        float v = __uint_as_float((unsigned)w) - tau;
        for (int c = 0; c < n; c++) {
            yl[c * PAD] = fmaxf(v, 0.0f);
            const bool adv = ((c + 1) > e);
            j += (int)adv;
            w = adv ? wn : w;
            e = (int)(w >> 32);
            v = __uint_as_float((unsigned)w) - tau;
            wn = segl[min(j + 1, SEG_ENTRIES - 1) * 32];   // prefetch
        }
    }
    __syncwarp();

    // ---- coalesced store ----
    float* dst = out + (size_t)rowBase * NCOLS;
    #pragma unroll 4
    for (int j = 0; j < ROWS_PER_BLK * NCOLS; j += 32) {
        int idx = j + lane;
        int r = idx >> 9;
        int c = idx & (NCOLS - 1);
        dst[idx] = ys[c * PAD + r];
    }
}

extern "C" void kernel_launch(void* const* d_in, const int* in_sizes, int n_in,
                              void* d_out, int out_size) {
    (void)in_sizes; (void)n_in; (void)out_size;
    const float* x   = (const float*)d_in[0];
    float*       out = (float*)d_out;

    cudaFuncSetAttribute(fusedmax_kernel,
                         cudaFuncAttributeMaxDynamicSharedMemorySize,
                         SMEM_BYTES);
    fusedmax_kernel<<<NROWS / ROWS_PER_BLK, ROWS_PER_BLK, SMEM_BYTES>>>(x, out);
}